// round 4
// baseline (speedup 1.0000x reference)
#include <cuda_runtime.h>
#include <math.h>

#define BB 8
#define NN 8192
#define SS 8
#define MROWS (BB * NN)          // 65536 tokens
#define DIN 64
#define DH  128                  // hidden
#define DOUT 64
#define ABC_COLS 384             // [A(128) | B(128) | C(128)]

// Scratch: ABC[m][0:128]=x@W1a, [128:256]=x@W1b, [256:384]=x@W1c  (96 MB)
__device__ float g_ABC[(size_t)MROWS * ABC_COLS];

__device__ __forceinline__ float gelu_exact(float x) {
    return 0.5f * x * (1.0f + erff(x * 0.7071067811865476f));
}

// ---------------------------------------------------------------------------
// Kernel 1: ABC = X (65536 x 64) @ W1-as-(64 x 384)
//   col tile == one 128-wide "part" (A/B/C), row tile = 128.
//   K=64 reduction split into 2 stages of K=32 to fit 48KB static smem.
//   256 threads, 8x8 register tile per thread.
//   XsT row padded to 132 floats to cut transpose-store bank conflicts.
// ---------------------------------------------------------------------------
__global__ __launch_bounds__(256) void k1_gemm(const float* __restrict__ X,
                                               const float* __restrict__ W1)
{
    __shared__ float XsT[32][132];   // [k][row]  (transposed on load), padded
    __shared__ float Ws [32][128];   // [k][col_local]

    const int tid  = threadIdx.x;
    const int m0   = blockIdx.x * 128;     // row tile base
    const int part = blockIdx.y;           // 0..2  -> W1 rows part*64 .. +63

    const int tx = tid & 15;               // col group
    const int ty = tid >> 4;               // row group
    float acc[8][8];
    #pragma unroll
    for (int i = 0; i < 8; i++)
        #pragma unroll
        for (int j = 0; j < 8; j++) acc[i][j] = 0.0f;

    #pragma unroll
    for (int kb = 0; kb < 2; kb++) {
        // Load X k-slice (128 rows x 32 k) = 1024 float4, transpose into XsT
        #pragma unroll
        for (int i = 0; i < 4; i++) {
            int lin = tid + i * 256;           // 0..1023
            int row = lin >> 3;                // 0..127
            int kq  = lin & 7;                 // 0..7 (float4 index along k-slice)
            float4 v = *(const float4*)&X[(size_t)(m0 + row) * DIN + kb * 32 + kq * 4];
            XsT[kq * 4 + 0][row] = v.x;
            XsT[kq * 4 + 1][row] = v.y;
            XsT[kq * 4 + 2][row] = v.z;
            XsT[kq * 4 + 3][row] = v.w;
        }
        // Load W k-slice: Ws[k][c] = W1[(part*64 + kb*32 + k)*128 + c]
        #pragma unroll
        for (int i = 0; i < 4; i++) {
            int lin = tid + i * 256;           // 0..1023
            int k   = lin >> 5;                // 0..31
            int cq  = lin & 31;                // 0..31 (float4 along 128 cols)
            *(float4*)&Ws[k][cq * 4] =
                *(const float4*)&W1[(size_t)(part * 64 + kb * 32 + k) * DH + cq * 4];
        }
        __syncthreads();

        #pragma unroll
        for (int k = 0; k < 32; k++) {
            float xv[8], wv[8];
            *(float4*)&xv[0] = *(const float4*)&XsT[k][ty * 8];
            *(float4*)&xv[4] = *(const float4*)&XsT[k][ty * 8 + 4];
            *(float4*)&wv[0] = *(const float4*)&Ws [k][tx * 8];
            *(float4*)&wv[4] = *(const float4*)&Ws [k][tx * 8 + 4];
            #pragma unroll
            for (int i = 0; i < 8; i++)
                #pragma unroll
                for (int j = 0; j < 8; j++)
                    acc[i][j] = fmaf(xv[i], wv[j], acc[i][j]);
        }
        __syncthreads();
    }

    // Store: rows m0+ty*8+i, global cols part*128 + tx*8 + j
    #pragma unroll
    for (int i = 0; i < 8; i++) {
        float* dst = &g_ABC[(size_t)(m0 + ty * 8 + i) * ABC_COLS + part * DH + tx * 8];
        *(float4*)&dst[0] = make_float4(acc[i][0], acc[i][1], acc[i][2], acc[i][3]);
        *(float4*)&dst[4] = make_float4(acc[i][4], acc[i][5], acc[i][6], acc[i][7]);
    }
}

// ---------------------------------------------------------------------------
// Kernel 2: per token m = b*N+n (one warp each):
//   g = (1/S) * sum_s gelu( A[m] + b1 + Bpart[j_s] + Cpart[k_s] )   (128-dim)
//   out[m] = g @ W2 + b2                                            (64-dim)
// ---------------------------------------------------------------------------
__global__ __launch_bounds__(256) void k2_fused(const int* __restrict__ j_idx,
                                                const int* __restrict__ k_idx,
                                                const float* __restrict__ W2,
                                                const float* __restrict__ b1,
                                                const float* __restrict__ b2,
                                                float* __restrict__ out)
{
    __shared__ float w2s[DH * DOUT];   // 32 KB, row-major [k][o]
    __shared__ float b1s[DH];
    __shared__ float b2s[DOUT];
    __shared__ float gbuf[8][DH];      // per-warp g staging

    const int tid = threadIdx.x;
    for (int i = tid; i < DH * DOUT; i += 256) w2s[i] = W2[i];
    if (tid < DH)   b1s[tid] = b1[tid];
    if (tid < DOUT) b2s[tid] = b2[tid];
    __syncthreads();

    const int warp = tid >> 5;
    const int lane = tid & 31;
    const int m    = blockIdx.x * 8 + warp;
    const int base = m & ~(NN - 1);     // b * N  (N power of two)

    // a = A[m][lane*4 .. +3] + b1
    const float* arow = &g_ABC[(size_t)m * ABC_COLS + lane * 4];
    float4 a  = *(const float4*)arow;
    float4 c1 = *(const float4*)&b1s[lane * 4];
    a.x += c1.x; a.y += c1.y; a.z += c1.z; a.w += c1.w;

    // indices (8 each) vectorized
    int4 j03 = *(const int4*)&j_idx[(size_t)m * SS];
    int4 j47 = *(const int4*)&j_idx[(size_t)m * SS + 4];
    int4 k03 = *(const int4*)&k_idx[(size_t)m * SS];
    int4 k47 = *(const int4*)&k_idx[(size_t)m * SS + 4];
    int js[8] = { j03.x, j03.y, j03.z, j03.w, j47.x, j47.y, j47.z, j47.w };
    int ks[8] = { k03.x, k03.y, k03.z, k03.w, k47.x, k47.y, k47.z, k47.w };

    float4 acc = make_float4(0.f, 0.f, 0.f, 0.f);
    #pragma unroll
    for (int s = 0; s < SS; s++) {
        const float* bp = &g_ABC[(size_t)(base + js[s]) * ABC_COLS + DH  + lane * 4];
        const float* cp = &g_ABC[(size_t)(base + ks[s]) * ABC_COLS + 2*DH + lane * 4];
        float4 vb = *(const float4*)bp;
        float4 vc = *(const float4*)cp;
        float hx = a.x + vb.x + vc.x;
        float hy = a.y + vb.y + vc.y;
        float hz = a.z + vb.z + vc.z;
        float hw = a.w + vb.w + vc.w;
        acc.x += gelu_exact(hx);
        acc.y += gelu_exact(hy);
        acc.z += gelu_exact(hz);
        acc.w += gelu_exact(hw);
    }
    acc.x *= 0.125f; acc.y *= 0.125f; acc.z *= 0.125f; acc.w *= 0.125f;

    *(float4*)&gbuf[warp][lane * 4] = acc;
    __syncwarp();

    // out[m][o], o = lane*2, lane*2+1 :  sum_k g[k] * W2[k][o]
    const int o = lane * 2;
    float s0 = 0.f, s1 = 0.f;
    #pragma unroll 16
    for (int k = 0; k < DH; k++) {
        float g  = gbuf[warp][k];                      // broadcast LDS
        float2 w = *(const float2*)&w2s[k * DOUT + o]; // conflict-free LDS.64
        s0 = fmaf(g, w.x, s0);
        s1 = fmaf(g, w.y, s1);
    }
    float2 r = make_float2(s0 + b2s[o], s1 + b2s[o + 1]);
    *(float2*)&out[(size_t)m * DOUT + o] = r;
}

// ---------------------------------------------------------------------------
extern "C" void kernel_launch(void* const* d_in, const int* in_sizes, int n_in,
                              void* d_out, int out_size)
{
    const float* x     = (const float*)d_in[0];
    const int*   j_idx = (const int*)  d_in[1];
    const int*   k_idx = (const int*)  d_in[2];
    const float* W1    = (const float*)d_in[3];
    const float* b1    = (const float*)d_in[4];
    const float* W2    = (const float*)d_in[5];
    const float* b2    = (const float*)d_in[6];
    float*       out   = (float*)d_out;

    dim3 g1(MROWS / 128, 3);
    k1_gemm<<<g1, 256>>>(x, W1);
    k2_fused<<<MROWS / 8, 256>>>(j_idx, k_idx, W2, b1, b2, out);
}